// round 17
// baseline (speedup 1.0000x reference)
#include <cuda_runtime.h>
#include <cuda_fp16.h>
#include <math.h>
#include <stdint.h>

#define SEQ 2048
#define HID 3584
#define NH 28
#define NKV 4
#define GRP 7
#define HD 128
#define SCALE_LG2  0.12751500885282288f     // (1/sqrt(128)) * log2(e)

// ---------------- scratch (static device globals; no runtime allocation) ----
__device__ __half g_hid_t[SEQ * HID];
__device__ __half g_wq_t[NH * HD * HID];
__device__ __half g_wk_t[NKV * HD * HID];
__device__ __half g_wv_t[NKV * HD * HID];
__device__ __half g_wo_t[HID * NH * HD];
__device__ float  g_q[SEQ * NH * HD];        // Q pre-rope fp32
__device__ float  g_k[SEQ * NKV * HD];       // K pre-rope fp32
__device__ __half g_qt[SEQ * NH * HD];       // rope(Q) fp16
__device__ __half g_kt[SEQ * NKV * HD];      // rope(K) fp16
__device__ __half g_vtT[NKV * HD * SEQ];     // V fp16 TRANSPOSED [h*d][s]
__device__ __half g_ot[SEQ * NH * HD];       // attn out fp16

// ---------------- helpers ----------------------------------------------------
__device__ __forceinline__ void mma_f16(float* c, const uint32_t* a, const uint32_t* b) {
    asm volatile(
        "mma.sync.aligned.m16n8k16.row.col.f32.f16.f16.f32 "
        "{%0,%1,%2,%3}, {%4,%5,%6,%7}, {%8,%9}, {%0,%1,%2,%3};"
        : "+f"(c[0]), "+f"(c[1]), "+f"(c[2]), "+f"(c[3])
        : "r"(a[0]), "r"(a[1]), "r"(a[2]), "r"(a[3]), "r"(b[0]), "r"(b[1]));
}
__device__ __forceinline__ void ldsm4(uint32_t* r, uint32_t addr) {
    asm volatile("ldmatrix.sync.aligned.m8n8.x4.shared.b16 {%0,%1,%2,%3}, [%4];"
        : "=r"(r[0]), "=r"(r[1]), "=r"(r[2]), "=r"(r[3]) : "r"(addr));
}
__device__ __forceinline__ uint32_t smem_u32(const void* p) {
    return (uint32_t)__cvta_generic_to_shared(p);
}
__device__ __forceinline__ void cp16(uint32_t s, const void* g) {
    asm volatile("cp.async.cg.shared.global [%0], [%1], 16;" :: "r"(s), "l"(g));
}
#define CP_COMMIT() asm volatile("cp.async.commit_group;" ::: "memory")
#define CP_WAIT(n)  asm volatile("cp.async.wait_group %0;" :: "n"(n) : "memory")

// ---------------- single fused fp32 -> fp16 converter ------------------------
#define CN0 ((long)SEQ * HID)
#define CN1 ((long)NH * HD * HID)
#define CN2 ((long)NKV * HD * HID)
#define CTOT (CN0 + CN1 + 2 * CN2 + CN1)

__global__ void conv_all(const float* __restrict__ h, const float* __restrict__ wq,
                         const float* __restrict__ wk, const float* __restrict__ wv,
                         const float* __restrict__ wo)
{
    long i = ((long)blockIdx.x * blockDim.x + threadIdx.x) * 8;
    const float* s; __half* d; long off;
    if (i < CN0)                       { s = h;  d = g_hid_t; off = i; }
    else if (i < CN0 + CN1)            { s = wq; d = g_wq_t;  off = i - CN0; }
    else if (i < CN0 + CN1 + CN2)      { s = wk; d = g_wk_t;  off = i - CN0 - CN1; }
    else if (i < CN0 + CN1 + 2 * CN2)  { s = wv; d = g_wv_t;  off = i - CN0 - CN1 - CN2; }
    else                               { s = wo; d = g_wo_t;  off = i - CN0 - CN1 - 2 * CN2; }
    float4 x = *(const float4*)(s + off);
    float4 y = *(const float4*)(s + off + 4);
    __half hh[8] = { __float2half_rn(x.x), __float2half_rn(x.y),
                     __float2half_rn(x.z), __float2half_rn(x.w),
                     __float2half_rn(y.x), __float2half_rn(y.y),
                     __float2half_rn(y.z), __float2half_rn(y.w) };
    *(uint4*)(d + off) = *(uint4*)hh;
}

// ---------------- rope + fp16 (coalesced, natural layout) --------------------
__global__ void prep_rope(const float* __restrict__ cosT, const float* __restrict__ sinT)
{
    const int s = blockIdx.x, d = threadIdx.x;
    const float c  = cosT[s * HD + d];
    const float sn = sinT[s * HD + d];
    const float sg = (d < 64) ? -1.f : 1.f;

#pragma unroll
    for (int i = 0; i < 7; i++) {
        int h = blockIdx.y * 7 + i;
        size_t base = ((size_t)s * NH + h) * HD;
        float x  = g_q[base + d];
        float xo = g_q[base + (d ^ 64)];
        g_qt[base + d] = __float2half_rn(fmaf(sg * xo, sn, x * c));
    }
    {
        size_t base = ((size_t)s * NKV + blockIdx.y) * HD;
        float x  = g_k[base + d];
        float xo = g_k[base + (d ^ 64)];
        g_kt[base + d] = __float2half_rn(fmaf(sg * xo, sn, x * c));
    }
}

// ---------------- FP16 tensor GEMM: 128x128 block, warp 64x32, 2 stages ------
// 2-stage pipeline: smem 73.7KB -> 3 CTAs/SM (regs capped at 84 by bounds).
#define GSTRh 72
#define GSTAGEh (128 * GSTRh)
#define GEMM_SMEM (2 * GSTAGEh * 2 * 2)   // 73728 bytes

// MODE: 0 = fp32 out + bias, 1 = V: fp16 transposed out + bias, 2 = fp32 no bias
template <int MODE>
__device__ __forceinline__ void gemm_body(
    const __half* __restrict__ A, const __half* __restrict__ B,
    const float* __restrict__ bias, void* __restrict__ C,
    int N, int K, int bx, int by, __half* As, __half* Bs)
{
    const int tid  = threadIdx.x;
    const int warp = tid >> 5, lane = tid & 31;
    const int wm = (warp >> 2) * 64;
    const int wn = (warp & 3) * 32;
    const int arow = lane & 15, acol = (lane >> 4) << 3;
    const int brow = lane & 7, bk8 = ((lane >> 3) & 1) << 3;
    const int bnt  = lane >> 4;

    float acc[16][4];
#pragma unroll
    for (int i = 0; i < 16; i++)
#pragma unroll
        for (int j = 0; j < 4; j++) acc[i][j] = 0.f;

    const int T = K / 64;

#define LOAD_TILE(t_)                                                            \
    do {                                                                         \
        __half* ab_ = As + ((t_) & 1) * GSTAGEh;                                 \
        __half* bb_ = Bs + ((t_) & 1) * GSTAGEh;                                 \
        _Pragma("unroll")                                                        \
        for (int i_ = 0; i_ < 4; i_++) {                                         \
            int f_ = tid + i_ * 256;                                             \
            int row_ = f_ >> 3, ch_ = (f_ & 7) * 8;                              \
            cp16(smem_u32(ab_ + row_ * GSTRh + ch_),                             \
                 A + (size_t)(by * 128 + row_) * K + (t_) * 64 + ch_);           \
            cp16(smem_u32(bb_ + row_ * GSTRh + ch_),                             \
                 B + (size_t)(bx * 128 + row_) * K + (t_) * 64 + ch_);           \
        }                                                                        \
        CP_COMMIT();                                                             \
    } while (0)

    LOAD_TILE(0);

    for (int t = 0; t < T; t++) {
        if (t + 1 < T) { LOAD_TILE(t + 1); CP_WAIT(1); }
        else           { CP_WAIT(0); }
        __syncthreads();                 // tile t ready

        const __half* as = As + (t & 1) * GSTAGEh;
        const __half* bs = Bs + (t & 1) * GSTAGEh;
#pragma unroll
        for (int kk = 0; kk < 64; kk += 16) {
            uint32_t a[4][4], bb[2][4];
#pragma unroll
            for (int mt = 0; mt < 4; mt++)
                ldsm4(a[mt], smem_u32(as + (wm + mt * 16 + arow) * GSTRh + kk + acol));
#pragma unroll
            for (int np = 0; np < 2; np++)
                ldsm4(bb[np], smem_u32(bs + (wn + (np * 2 + bnt) * 8 + brow) * GSTRh + kk + bk8));
#pragma unroll
            for (int mt = 0; mt < 4; mt++)
#pragma unroll
                for (int nt = 0; nt < 4; nt++)
                    mma_f16(acc[mt * 4 + nt], a[mt], &bb[nt >> 1][(nt & 1) * 2]);
        }
        __syncthreads();                 // tile t consumed; next load may overwrite
    }

#pragma unroll
    for (int mt = 0; mt < 4; mt++) {
#pragma unroll
        for (int nt = 0; nt < 4; nt++) {
            int r0 = by * 128 + wm + mt * 16 + (lane >> 2);
            int c0 = bx * 128 + wn + nt * 8 + 2 * (lane & 3);
            float b0 = (MODE != 2) ? bias[c0] : 0.f;
            float b1 = (MODE != 2) ? bias[c0 + 1] : 0.f;
            float* ca = acc[mt * 4 + nt];
            if (MODE == 1) {
                __half* Co = (__half*)C;   // g_vtT: [c][s]
                Co[(size_t)c0 * SEQ + r0]           = __float2half_rn(ca[0] + b0);
                Co[(size_t)(c0 + 1) * SEQ + r0]     = __float2half_rn(ca[1] + b1);
                Co[(size_t)c0 * SEQ + r0 + 8]       = __float2half_rn(ca[2] + b0);
                Co[(size_t)(c0 + 1) * SEQ + r0 + 8] = __float2half_rn(ca[3] + b1);
            } else {
                float* Co = (float*)C;
                *(float2*)(&Co[(size_t)r0 * N + c0])       = make_float2(ca[0] + b0, ca[1] + b1);
                *(float2*)(&Co[(size_t)(r0 + 8) * N + c0]) = make_float2(ca[2] + b0, ca[3] + b1);
            }
        }
    }
#undef LOAD_TILE
}

__global__ __launch_bounds__(256, 3) void gemm_qkv(
    const float* __restrict__ bq, const float* __restrict__ bk,
    const float* __restrict__ bv)
{
    extern __shared__ __align__(16) __half gsm[];
    __half* As = gsm;
    __half* Bs = gsm + 2 * GSTAGEh;
    const int bx = blockIdx.x, by = blockIdx.y;
    if (bx < 28)
        gemm_body<0>(g_hid_t, g_wq_t, bq, g_q, NH * HD, HID, bx, by, As, Bs);
    else if (bx < 32)
        gemm_body<0>(g_hid_t, g_wk_t, bk, g_k, NKV * HD, HID, bx - 28, by, As, Bs);
    else
        gemm_body<1>(g_hid_t, g_wv_t, bv, g_vtT, NKV * HD, HID, bx - 32, by, As, Bs);
}

__global__ __launch_bounds__(256, 3) void gemm_out(float* __restrict__ C)
{
    extern __shared__ __align__(16) __half gsm[];
    gemm_body<2>(g_ot, g_wo_t, nullptr, C, HID, HID, blockIdx.x, blockIdx.y,
                 gsm, gsm + 2 * GSTAGEh);
}

// ---------------- Flash attention (doc-aware tile skipping) ------------------
#define QSTRh 136
#define KSTRh 136
#define VTSTRh 72
#define PSTRh 72
#define KVTILEh (64 * KSTRh)
#define FLASH_SMEM ((128*QSTRh + 2*KVTILEh + 128*VTSTRh + 128*PSTRh) * 2 + 64 * 4)

__global__ __launch_bounds__(256) void flash_kernel(const int* __restrict__ doc)
{
    extern __shared__ __align__(16) __half fsm[];
    __half* Qs  = fsm;                        // [128][QSTRh]
    __half* Ks  = Qs + 128 * QSTRh;           // 2 x [64][KSTRh]
    __half* VTs = Ks + 2 * KVTILEh;           // [128 d][VTSTRh]
    __half* Ps  = VTs + 128 * VTSTRh;         // [128][PSTRh]
    int* kdoc = (int*)(Ps + 128 * PSTRh);

    const int qb = gridDim.x - 1 - blockIdx.x;
    const int head = blockIdx.y;
    const int kvh = head / GRP;
    const int q0 = qb * 128;
    const int tid = threadIdx.x;
    const int warp = tid >> 5, lane = tid & 31;
    const int g = lane >> 2, tg = lane & 3;
    const int m0 = warp * 16;
    const int arow = lane & 15, acol = (lane >> 4) << 3;
    const int brow = lane & 7, bk8 = ((lane >> 3) & 1) << 3;
    const int bnt  = lane >> 4;

    // doc-aware start tile
    const int dq_lo = __ldg(doc + q0), dq_hi = __ldg(doc + q0 + 127);
    int lo = 0, hi = q0;
    while (lo < hi) {
        int mid = (lo + hi) >> 1;
        if (__ldg(doc + mid) < dq_lo) lo = mid + 1; else hi = mid;
    }
    const int t0 = lo >> 6;
    const int tmax = 2 * qb + 1;
    const bool q_split = (dq_lo != dq_hi);

    for (int f = tid; f < 128 * 16; f += 256) {
        int row = f >> 4, c8 = (f & 15) * 8;
        cp16(smem_u32(Qs + row * QSTRh + c8),
             g_qt + ((size_t)(q0 + row) * NH + head) * HD + c8);
    }
    CP_COMMIT();
    for (int f = tid; f < 64 * 16; f += 256) {
        int row = f >> 4, c8 = (f & 15) * 8;
        cp16(smem_u32(Ks + row * KSTRh + c8),
             g_kt + ((size_t)(t0 * 64 + row) * NKV + kvh) * HD + c8);
    }
    CP_COMMIT();
    for (int f = tid; f < 128 * 8; f += 256) {
        int d = f >> 3, c8 = (f & 7) * 8;
        cp16(smem_u32(VTs + d * VTSTRh + c8),
             g_vtT + ((size_t)(kvh * HD + d)) * SEQ + t0 * 64 + c8);
    }
    CP_COMMIT();

    const int qr0 = q0 + m0 + g, qr1 = qr0 + 8;
    const int qd0 = __ldg(doc + qr0), qd1 = __ldg(doc + qr1);
    float mi0 = -1e30f, mi1 = -1e30f, li0 = 0.f, li1 = 0.f;
    float o[16][4];
#pragma unroll
    for (int i = 0; i < 16; i++)
#pragma unroll
        for (int j = 0; j < 4; j++) o[i][j] = 0.f;

    for (int t = t0; t <= tmax; t++) {
        const int k0 = t * 64;
        const int dk_lo = __ldg(doc + k0), dk_hi = __ldg(doc + k0 + 63);
        const bool need_mask = (t >= 2 * qb) | (dk_lo != dk_hi) |
                               (dk_lo != dq_lo) | q_split;
        if (need_mask && tid < 64) kdoc[tid] = doc[k0 + tid];
        CP_WAIT(1);
        __syncthreads();

        const __half* ks = Ks + (t & 1) * KVTILEh;

        float s[8][4];
#pragma unroll
        for (int i = 0; i < 8; i++)
#pragma unroll
            for (int j = 0; j < 4; j++) s[i][j] = 0.f;

#pragma unroll
        for (int kk = 0; kk < 128; kk += 16) {
            uint32_t a[4];
            ldsm4(a, smem_u32(Qs + (m0 + arow) * QSTRh + kk + acol));
#pragma unroll
            for (int np = 0; np < 4; np++) {
                uint32_t bb[4];
                ldsm4(bb, smem_u32(ks + ((np * 2 + bnt) * 8 + brow) * KSTRh + kk + bk8));
                mma_f16(s[np * 2 + 0], a, bb);
                mma_f16(s[np * 2 + 1], a, bb + 2);
            }
        }

        float mx0 = -1e30f, mx1 = -1e30f;
        if (need_mask) {
#pragma unroll
            for (int nt = 0; nt < 8; nt++) {
                int c0 = k0 + nt * 8 + 2 * tg;
                int d0 = kdoc[nt * 8 + 2 * tg];
                int d1 = kdoc[nt * 8 + 2 * tg + 1];
                s[nt][0] = (qr0 >= c0     && qd0 == d0) ? s[nt][0] * SCALE_LG2 : -1e30f;
                s[nt][1] = (qr0 >= c0 + 1 && qd0 == d1) ? s[nt][1] * SCALE_LG2 : -1e30f;
                s[nt][2] = (qr1 >= c0     && qd1 == d0) ? s[nt][2] * SCALE_LG2 : -1e30f;
                s[nt][3] = (qr1 >= c0 + 1 && qd1 == d1) ? s[nt][3] * SCALE_LG2 : -1e30f;
                mx0 = fmaxf(mx0, fmaxf(s[nt][0], s[nt][1]));
                mx1 = fmaxf(mx1, fmaxf(s[nt][2], s[nt][3]));
            }
        } else {
#pragma unroll
            for (int nt = 0; nt < 8; nt++) {
                s[nt][0] *= SCALE_LG2; s[nt][1] *= SCALE_LG2;
                s[nt][2] *= SCALE_LG2; s[nt][3] *= SCALE_LG2;
                mx0 = fmaxf(mx0, fmaxf(s[nt][0], s[nt][1]));
                mx1 = fmaxf(mx1, fmaxf(s[nt][2], s[nt][3]));
            }
        }
        mx0 = fmaxf(mx0, __shfl_xor_sync(0xffffffffu, mx0, 1));
        mx0 = fmaxf(mx0, __shfl_xor_sync(0xffffffffu, mx0, 2));
        mx1 = fmaxf(mx1, __shfl_xor_sync(0xffffffffu, mx1, 1));
        mx1 = fmaxf(mx1, __shfl_xor_sync(0xffffffffu, mx1, 2));

        float nm0 = fmaxf(mi0, mx0), nm1 = fmaxf(mi1, mx1);
        float cr0 = exp2f(mi0 - nm0), cr1 = exp2f(mi1 - nm1);
        mi0 = nm0; mi1 = nm1;
#pragma unroll
        for (int nt = 0; nt < 16; nt++) {
            o[nt][0] *= cr0; o[nt][1] *= cr0;
            o[nt][2] *= cr1; o[nt][3] *= cr1;
        }

        float rs0 = 0.f, rs1 = 0.f;
#pragma unroll
        for (int nt = 0; nt < 8; nt++) {
            float pe0 = (s[nt][0] > -1e29f) ? exp2f(s[nt][0] - nm0) : 0.f;
            float pe1 = (s[nt][1] > -1e29f) ? exp2f(s[nt][1] - nm0) : 0.f;
            float pe2 = (s[nt][2] > -1e29f) ? exp2f(s[nt][2] - nm1) : 0.f;
            float pe3 = (s[nt][3] > -1e29f) ? exp2f(s[nt][3] - nm1) : 0.f;
            rs0 += pe0 + pe1; rs1 += pe2 + pe3;
            int c = nt * 8 + 2 * tg;
            *(__half2*)(Ps + (m0 + g) * PSTRh + c)     = __floats2half2_rn(pe0, pe1);
            *(__half2*)(Ps + (m0 + 8 + g) * PSTRh + c) = __floats2half2_rn(pe2, pe3);
        }
        rs0 += __shfl_xor_sync(0xffffffffu, rs0, 1);
        rs0 += __shfl_xor_sync(0xffffffffu, rs0, 2);
        rs1 += __shfl_xor_sync(0xffffffffu, rs1, 1);
        rs1 += __shfl_xor_sync(0xffffffffu, rs1, 2);
        li0 = li0 * cr0 + rs0;
        li1 = li1 * cr1 + rs1;

        if (t < tmax) {
            const int kn = k0 + 64;
            __half* kd = Ks + ((t + 1) & 1) * KVTILEh;
            for (int f = tid; f < 64 * 16; f += 256) {
                int row = f >> 4, c8 = (f & 15) * 8;
                cp16(smem_u32(kd + row * KSTRh + c8),
                     g_kt + ((size_t)(kn + row) * NKV + kvh) * HD + c8);
            }
            CP_COMMIT();
            CP_WAIT(1);
        } else {
            CP_WAIT(0);
        }
        __syncthreads();

#pragma unroll
        for (int kk = 0; kk < 64; kk += 16) {
            uint32_t a[4];
            ldsm4(a, smem_u32(Ps + (m0 + arow) * PSTRh + kk + acol));
#pragma unroll
            for (int np = 0; np < 8; np++) {
                uint32_t bb[4];
                ldsm4(bb, smem_u32(VTs + ((np * 2 + bnt) * 8 + brow) * VTSTRh + kk + bk8));
                mma_f16(o[np * 2 + 0], a, bb);
                mma_f16(o[np * 2 + 1], a, bb + 2);
            }
        }
        __syncthreads();

        if (t < tmax) {
            const int kn = k0 + 64;
            for (int f = tid; f < 128 * 8; f += 256) {
                int d = f >> 3, c8 = (f & 7) * 8;
                cp16(smem_u32(VTs + d * VTSTRh + c8),
                     g_vtT + ((size_t)(kvh * HD + d)) * SEQ + kn + c8);
            }
            CP_COMMIT();
        }
    }

    float inv0 = 1.f / li0, inv1 = 1.f / li1;
#pragma unroll
    for (int nt = 0; nt < 16; nt++) {
        int c = nt * 8 + 2 * tg;
        size_t b0 = ((size_t)qr0 * NH + head) * HD + c;
        size_t b1 = ((size_t)qr1 * NH + head) * HD + c;
        *(__half2*)(g_ot + b0) = __floats2half2_rn(o[nt][0] * inv0, o[nt][1] * inv0);
        *(__half2*)(g_ot + b1) = __floats2half2_rn(o[nt][2] * inv1, o[nt][3] * inv1);
    }
}

// ---------------- launch -----------------------------------------------------
extern "C" void kernel_launch(void* const* d_in, const int* in_sizes, int n_in,
                              void* d_out, int out_size)
{
    const float* hidden = (const float*)d_in[0];
    const float* cosT   = (const float*)d_in[1];
    const float* sinT   = (const float*)d_in[2];
    const int*   doc    = (const int*)  d_in[3];
    const float* Wq = (const float*)d_in[5];
    const float* bq = (const float*)d_in[6];
    const float* Wk = (const float*)d_in[7];
    const float* bk = (const float*)d_in[8];
    const float* Wv = (const float*)d_in[9];
    const float* bv = (const float*)d_in[10];
    const float* Wo = (const float*)d_in[11];
    float* out = (float*)d_out;

    // 1) fused fp32 -> fp16 conversion (1 launch)
    conv_all<<<(int)(CTOT / 8 / 256), 256>>>(hidden, Wq, Wk, Wv, Wo);

    // 2) fused QKV projections (2-stage, 3 CTAs/SM)
    cudaFuncSetAttribute(gemm_qkv, cudaFuncAttributeMaxDynamicSharedMemorySize, GEMM_SMEM);
    gemm_qkv<<<dim3(36, SEQ / 128), 256, GEMM_SMEM>>>(bq, bk, bv);

    // 3) RoPE + fp16 for Q/K (coalesced)
    prep_rope<<<dim3(SEQ, 4), HD>>>(cosT, sinT);

    // 4) flash attention (doc-aware tile skipping)
    cudaFuncSetAttribute(flash_kernel, cudaFuncAttributeMaxDynamicSharedMemorySize, FLASH_SMEM);
    flash_kernel<<<dim3(SEQ / 128, NH), 256, FLASH_SMEM>>>(doc);

    // 5) output projection (2-stage, 3 CTAs/SM, single wave)
    cudaFuncSetAttribute(gemm_out, cudaFuncAttributeMaxDynamicSharedMemorySize, GEMM_SMEM);
    gemm_out<<<dim3(HID / 128, SEQ / 128), 256, GEMM_SMEM>>>(out);
}